// round 8
// baseline (speedup 1.0000x reference)
#include <cuda_runtime.h>
#include <math.h>
#include <stdint.h>

// Problem constants (fixed by the seeded reference):
//   m=8, nc=1024, nt=512, dim=2, PPU=64 -> grid 129x129 per batch.
#define M_B   8
#define NC    1024
#define NT    512
#define AX    129
#define NG    (AX * AX)            // 16641
#define HALF  64
#define INV_PPU (1.0f / 64.0f)
#define X_TOTAL (M_B * NG * 2)

#define NSPLIT 8                   // K-splits per CTA (2 warps each)
#define KSPL   (NC / NSPLIT)       // 128 contexts per split

#define SMEM_G 49152               // combine scratch (4 slots x 64 thr x 192B)

// Global factor tables (static __device__: no runtime allocation)
__device__ __align__(16) float  g_wxq[M_B * NC * 128];   // 4 MB   [b][c][i] i<128
__device__ __align__(16) float  g_wxe[M_B * NC];         // wx at i=128
__device__ __align__(16) float  g_wyt[M_B * NC * 384];   // 12.6MB [b][c][16jt][2jg][3ch][2jp][2e]
__device__ __align__(16) float  g_wyc[M_B * NC * 3];     // wy at j=128: {w*y0, w*y1, w}
__device__ float2 g_mid[M_B];

__device__ __forceinline__ float ex2f(float x) {
    float r; asm("ex2.approx.f32 %0, %1;" : "=f"(r) : "f"(x)); return r;
}
__device__ __forceinline__ float soft_k(float p) {
    // weight = 2^(-((d*k)^2)), k = sqrt(0.5*log2(e)) / (1e-5 + softplus(p))
    float ls = 1e-5f + log1pf(expf(p));
    return sqrtf(0.5f * 1.44269504088896341f) / ls;
}
__device__ __forceinline__ uint32_t sm32(const void* p) {
    uint32_t a;
    asm("{ .reg .u64 t; cvta.to.shared.u64 t, %1; cvt.u32.u64 %0, t; }" : "=r"(a) : "l"(p));
    return a;
}
#define FMA2(acc, a, b) \
    asm("fma.rn.f32x2 %0, %1, %2, %0;" : "+l"(acc) : "l"(a), "l"(b))
#define ADD2(acc, p) \
    asm("add.rn.f32x2 %0, %0, %1;" : "+l"(acc) : "l"(p))
#define PACK2(d, w) \
    asm("mov.b64 %0, {%1, %1};" : "=l"(d) : "f"(w))

// ------------------- Kernel 1: build factor tables -------------------
__global__ void __launch_bounds__(256) fill_kernel(const float* __restrict__ xc,
                                                   const float* __restrict__ yc,
                                                   const float* __restrict__ xt,
                                                   const float* __restrict__ lsp) {
    const int b  = blockIdx.x >> 5;
    const int sl = blockIdx.x & 31;     // 32 contexts per CTA
    const int tid = threadIdx.x;
    const int w = tid >> 5, l = tid & 31;

    // redundant per-batch min/max over concat(xc, xt)
    float mn0 = 1e30f, mx0 = -1e30f, mn1 = 1e30f, mx1 = -1e30f;
    for (int idx = tid; idx < NC + NT; idx += 256) {
        const float2 p = (idx < NC)
            ? *(const float2*)(xc + (size_t)(b * NC + idx) * 2)
            : *(const float2*)(xt + (size_t)(b * NT + idx - NC) * 2);
        mn0 = fminf(mn0, p.x); mx0 = fmaxf(mx0, p.x);
        mn1 = fminf(mn1, p.y); mx1 = fmaxf(mx1, p.y);
    }
    for (int o = 16; o; o >>= 1) {
        mn0 = fminf(mn0, __shfl_xor_sync(~0u, mn0, o));
        mx0 = fmaxf(mx0, __shfl_xor_sync(~0u, mx0, o));
        mn1 = fminf(mn1, __shfl_xor_sync(~0u, mn1, o));
        mx1 = fmaxf(mx1, __shfl_xor_sync(~0u, mx1, o));
    }
    __shared__ float s[4][8];
    __shared__ float2 smid;
    if (l == 0) { s[0][w] = mn0; s[1][w] = mx0; s[2][w] = mn1; s[3][w] = mx1; }
    __syncthreads();
    if (tid == 0) {
        float a = s[0][0], bb = s[1][0], c = s[2][0], d = s[3][0];
        #pragma unroll
        for (int k = 1; k < 8; k++) {
            a = fminf(a, s[0][k]); bb = fmaxf(bb, s[1][k]);
            c = fminf(c, s[2][k]); d = fmaxf(d, s[3][k]);
        }
        smid = make_float2(0.5f * (a + bb), 0.5f * (c + d));
        g_mid[b] = smid;     // benign identical-value race across CTAs of same b
    }
    __syncthreads();
    const float2 mid = smid;
    const float k0 = soft_k(lsp[0]);
    const float k1 = soft_k(lsp[1]);

    const int cl  = tid >> 3;     // 0..31 local context
    const int sub = tid & 7;      // 8 threads per context
    const int c = sl * 32 + cl;
    const float2 v  = *(const float2*)(xc + (size_t)(b * NC + c) * 2);
    const float2 yv = *(const float2*)(yc + (size_t)(b * NC + c) * 2);

    // wx: i = 0..128
    float* wxrow = g_wxq + (size_t)(b * NC + c) * 128;
    for (int i = sub; i <= 128; i += 8) {
        const float d = (mid.x + (float)(i - HALF) * INV_PPU - v.x) * k0;
        const float wv = ex2f(-(d * d));
        if (i < 128) wxrow[i] = wv;
        else         g_wxe[b * NC + c] = wv;
    }
    // wy: j = 0..128; layout per (b,c): [jt 16][jg 2][ch 3][jp 2][e 2] floats
    float* wyrow = g_wyt + (size_t)(b * NC + c) * 384;
    for (int j = sub; j <= 128; j += 8) {
        const float d = (mid.y + (float)(j - HALF) * INV_PPU - v.y) * k1;
        const float wv = ex2f(-(d * d));
        if (j < 128) {
            const int f = (j >> 3) * 24 + ((j >> 2) & 1) * 12 + ((j >> 1) & 1) * 2 + (j & 1);
            wyrow[f] = wv * yv.x; wyrow[f + 4] = wv * yv.y; wyrow[f + 8] = wv;
        } else {
            float* wc = g_wyc + (size_t)(b * NC + c) * 3;
            wc[0] = wv * yv.x; wc[1] = wv * yv.y; wc[2] = wv;
        }
    }
}

// ------------------- Kernel 2: batched GEMM straight from L2 -------------------
extern __shared__ char dynsm[];

__global__ void __launch_bounds__(512, 1)
gemm_kernel(float* __restrict__ out) {
    const int b = blockIdx.y;
    const int jt = blockIdx.x;        // 0..15 main, 16 = edge CTA
    const int tid = threadIdx.x;
    const float2 mid = g_mid[b];
    const uint32_t smb = sm32(dynsm);

    if (jt < 16) {
        const int w = tid >> 5, lane = tid & 31;
        const int s = w >> 1, jg = w & 1;       // split 0..7, j-group 0..1

        const float* wxp = g_wxq + ((size_t)(b * NC) + (size_t)s * KSPL) * 128;
        const float* wyp = g_wyt + ((size_t)(b * NC) + (size_t)s * KSPL) * 384
                         + jt * 24 + jg * 12;

        unsigned long long acc[24];           // [i 0..3][pair 0..1][ch 0..2]
        #pragma unroll
        for (int q = 0; q < 24; q++) acc[q] = 0;

        #pragma unroll 4
        for (int c = 0; c < KSPL; c++) {
            const float4 wxv = __ldg((const float4*)(wxp + (size_t)c * 128) + lane);
            const ulonglong2 q0 = __ldg((const ulonglong2*)(wyp + (size_t)c * 384));
            const ulonglong2 q1 = __ldg((const ulonglong2*)(wyp + (size_t)c * 384 + 4));
            const ulonglong2 q2 = __ldg((const ulonglong2*)(wyp + (size_t)c * 384 + 8));
            unsigned long long d0, d1, d2, d3;
            PACK2(d0, wxv.x); PACK2(d1, wxv.y); PACK2(d2, wxv.z); PACK2(d3, wxv.w);
            FMA2(acc[0],  d0, q0.x); FMA2(acc[1],  d0, q1.x); FMA2(acc[2],  d0, q2.x);
            FMA2(acc[3],  d0, q0.y); FMA2(acc[4],  d0, q1.y); FMA2(acc[5],  d0, q2.y);
            FMA2(acc[6],  d1, q0.x); FMA2(acc[7],  d1, q1.x); FMA2(acc[8],  d1, q2.x);
            FMA2(acc[9],  d1, q0.y); FMA2(acc[10], d1, q1.y); FMA2(acc[11], d1, q2.y);
            FMA2(acc[12], d2, q0.x); FMA2(acc[13], d2, q1.x); FMA2(acc[14], d2, q2.x);
            FMA2(acc[15], d2, q0.y); FMA2(acc[16], d2, q1.y); FMA2(acc[17], d2, q2.y);
            FMA2(acc[18], d3, q0.x); FMA2(acc[19], d3, q1.x); FMA2(acc[20], d3, q2.x);
            FMA2(acc[21], d3, q0.y); FMA2(acc[22], d3, q1.y); FMA2(acc[23], d3, q2.y);
        }

        // ---- tree-combine the 8 split partials through smem ----
        auto store_accs = [&](int slot) {
            const uint32_t a = smb + (uint32_t)((slot * 64 + jg * 32 + lane) * 192);
            #pragma unroll
            for (int q = 0; q < 12; q++)
                asm volatile("st.shared.v2.u64 [%0], {%1,%2};"
                             :: "r"(a + q * 16), "l"(acc[2 * q]), "l"(acc[2 * q + 1]) : "memory");
        };
        auto add_accs = [&](int slot) {
            const uint32_t a = smb + (uint32_t)((slot * 64 + jg * 32 + lane) * 192);
            #pragma unroll
            for (int q = 0; q < 12; q++) {
                unsigned long long p0, p1;
                asm("ld.shared.v2.u64 {%0,%1}, [%2];" : "=l"(p0), "=l"(p1) : "r"(a + q * 16));
                ADD2(acc[2 * q], p0); ADD2(acc[2 * q + 1], p1);
            }
        };
        __syncthreads();
        if (s >= 4) store_accs(s - 4);
        __syncthreads();
        if (s < 4) add_accs(s);
        __syncthreads();
        if (s == 2 || s == 3) store_accs(s - 2);
        __syncthreads();
        if (s < 2) add_accs(s);
        __syncthreads();
        if (s == 1) store_accs(0);
        __syncthreads();

        if (s == 0) {
            add_accs(0);
            // write z for this thread's 4i x 4j x 3ch tile
            const int j0 = jt * 8 + jg * 4;
            union { unsigned long long u; float f[2]; } v;
            #pragma unroll
            for (int ii = 0; ii < 4; ii++) {
                const int i = 4 * lane + ii;
                const size_t rb = (size_t)X_TOTAL + ((size_t)(b * NG) + (size_t)i * AX + j0) * 3;
                #pragma unroll
                for (int p = 0; p < 2; p++) {
                    #pragma unroll
                    for (int ch = 0; ch < 3; ch++) {
                        v.u = acc[ii * 6 + p * 3 + ch];
                        out[rb + (2 * p) * 3 + ch]     = v.f[0];
                        out[rb + (2 * p + 1) * 3 + ch] = v.f[1];
                    }
                }
            }
        }
        // x_grid for CTA region (all 512 threads, 2 points each)
        #pragma unroll
        for (int r = 0; r < 2; r++) {
            const int idx = tid + 512 * r;
            const int i = idx >> 3, jj = idx & 7;
            const int j = jt * 8 + jj;
            float2* xg = (float2*)out + (size_t)(b * NG) + (size_t)i * AX + j;
            *xg = make_float2(mid.x + (float)(i - HALF) * INV_PPU,
                              mid.y + (float)(j - HALF) * INV_PPU);
        }
    } else {
        // ---------------- edge CTA: i = 128 row (all j) + j = 128 col (i<128) ----
        float* swxe  = (float*)dynsm;               // 1024 floats
        float* swyc  = (float*)(dynsm + 4096);      // 1024 x 3 (wy at j=128)
        float* part  = (float*)(dynsm + 17408);     // 257 x 3 partials
        for (int idx = tid; idx < NC; idx += 512)
            swxe[idx] = __ldg(g_wxe + b * NC + idx);
        for (int idx = tid; idx < NC * 3; idx += 512)
            swyc[idx] = __ldg(g_wyc + (size_t)(b * NC) * 3 + idx);
        __syncthreads();

        const int m0 = tid >> 1, kh = tid & 1;
        const int nit = (m0 == 255) ? 2 : 1;
        const float* wyg = g_wyt + (size_t)(b * NC) * 384;
        const float* xqg = g_wxq + (size_t)(b * NC) * 128;

        float res[2][3];
        for (int q = 0; q < nit; q++) {
            const int m = m0 + q;
            float a0 = 0.f, a1 = 0.f, a2 = 0.f;
            const int cb = kh * 512;
            if (m < AX - 1) {        // row i=128, j=m (m < 128)
                const int f = (m >> 3) * 24 + ((m >> 2) & 1) * 12 + ((m >> 1) & 1) * 2 + (m & 1);
                #pragma unroll 4
                for (int c = cb; c < cb + 512; c++) {
                    const float wv = swxe[c];
                    const float* p = wyg + (size_t)c * 384 + f;
                    a0 = fmaf(wv, __ldg(p),     a0);
                    a1 = fmaf(wv, __ldg(p + 4), a1);
                    a2 = fmaf(wv, __ldg(p + 8), a2);
                }
            } else if (m == AX - 1) { // corner: i=128, j=128
                #pragma unroll 4
                for (int c = cb; c < cb + 512; c++) {
                    const float wv = swxe[c];
                    a0 = fmaf(wv, swyc[c * 3],     a0);
                    a1 = fmaf(wv, swyc[c * 3 + 1], a1);
                    a2 = fmaf(wv, swyc[c * 3 + 2], a2);
                }
            } else {                 // col j=128, i=m-129
                const int i = m - AX;
                #pragma unroll 4
                for (int c = cb; c < cb + 512; c++) {
                    const float wv = __ldg(xqg + (size_t)c * 128 + i);
                    a0 = fmaf(wv, swyc[c * 3],     a0);
                    a1 = fmaf(wv, swyc[c * 3 + 1], a1);
                    a2 = fmaf(wv, swyc[c * 3 + 2], a2);
                }
            }
            res[q][0] = a0; res[q][1] = a1; res[q][2] = a2;
        }
        if (kh == 1) {
            for (int q = 0; q < nit; q++) {
                const int m = m0 + q;
                part[m * 3] = res[q][0]; part[m * 3 + 1] = res[q][1]; part[m * 3 + 2] = res[q][2];
            }
        }
        __syncthreads();
        if (kh == 0) {
            for (int q = 0; q < nit; q++) {
                const int m = m0 + q;
                const float a0 = res[q][0] + part[m * 3];
                const float a1 = res[q][1] + part[m * 3 + 1];
                const float a2 = res[q][2] + part[m * 3 + 2];
                const int i = (m < AX) ? 128 : (m - AX);
                const int j = (m < AX) ? m : 128;
                const size_t zb = (size_t)X_TOTAL + ((size_t)(b * NG) + (size_t)i * AX + j) * 3;
                out[zb] = a0; out[zb + 1] = a1; out[zb + 2] = a2;
                float2* xg = (float2*)out + (size_t)(b * NG) + (size_t)i * AX + j;
                *xg = make_float2(mid.x + (float)(i - HALF) * INV_PPU,
                                  mid.y + (float)(j - HALF) * INV_PPU);
            }
        }
    }
}

extern "C" void kernel_launch(void* const* d_in, const int* in_sizes, int n_in,
                              void* d_out, int out_size) {
    const float* xc  = (const float*)d_in[0];
    const float* yc  = (const float*)d_in[1];
    const float* xt  = (const float*)d_in[2];
    const float* lsp = (const float*)d_in[3];
    float* out = (float*)d_out;

    cudaFuncSetAttribute(gemm_kernel, cudaFuncAttributeMaxDynamicSharedMemorySize, SMEM_G);
    fill_kernel<<<256, 256>>>(xc, yc, xt, lsp);
    gemm_kernel<<<dim3(17, M_B), 512, SMEM_G>>>(out);
}

// round 9
// speedup vs baseline: 1.5030x; 1.5030x over previous
#include <cuda_runtime.h>
#include <math.h>
#include <stdint.h>

// Problem constants (fixed by the seeded reference):
//   m=8, nc=1024, nt=512, dim=2, PPU=64 -> grid 129x129 per batch.
#define M_B   8
#define NC    1024
#define NT    512
#define AX    129
#define NG    (AX * AX)            // 16641
#define HALF  64
#define INV_PPU (1.0f / 64.0f)
#define X_TOTAL (M_B * NG * 2)
#define TOT_Z (M_B * NG * 3)       // 399384

#define NTHR  544                  // 17 warps: 16 main (4 ig x 4 jg) + 1 edge
#define KS    512                  // contexts per K-half
#define JTW   16                   // j columns per CTA
#define NJT   9                    // 9 x 16 = 144 j-slots >= 129

// Dynamic smem: wyy [512 c][3 ch][16 j] floats (98304 B) then cxk [512] (2048 B)
#define WYY_BYTES (KS * 192)
#define CXK_OFF   WYY_BYTES
#define SMEM_M    (WYY_BYTES + KS * 4)   // 100352

// K-split partial scratch: [ks 2][b 8][i 129][j 144][ch 3]
__device__ float g_part[2 * M_B * 129 * 144 * 3];   // 3.6 MB

__device__ __forceinline__ float ex2f(float x) {
    float r; asm("ex2.approx.f32 %0, %1;" : "=f"(r) : "f"(x)); return r;
}
__device__ __forceinline__ float soft_k(float p) {
    // weight = 2^(-((d*k)^2)), k = sqrt(0.5*log2(e)) / (1e-5 + softplus(p))
    float ls = 1e-5f + log1pf(expf(p));
    return sqrtf(0.5f * 1.44269504088896341f) / ls;
}
__device__ __forceinline__ uint32_t sm32(const void* p) {
    uint32_t a;
    asm("{ .reg .u64 t; cvta.to.shared.u64 t, %1; cvt.u32.u64 %0, t; }" : "=r"(a) : "l"(p));
    return a;
}
#define FMA2(acc, a, b) \
    asm("fma.rn.f32x2 %0, %1, %2, %0;" : "+l"(acc) : "l"(a), "l"(b))
#define PACK2(d, w) \
    asm("mov.b64 %0, {%1, %1};" : "=l"(d) : "f"(w))

extern __shared__ char dynsm[];

// ---------------- Main kernel: fused setconv with K-split partials ----------------
__global__ void __launch_bounds__(NTHR, 1)
main_kernel(const float* __restrict__ xc, const float* __restrict__ yc,
            const float* __restrict__ xt, const float* __restrict__ lsp,
            float* __restrict__ out) {
    const int ks = blockIdx.x & 1;          // K half
    const int jt = blockIdx.x >> 1;         // 0..8
    const int b  = blockIdx.y;
    const int tid = threadIdx.x;
    const int w = tid >> 5, l = tid & 31;
    const uint32_t smb = sm32(dynsm);
    float* wyyf  = (float*)dynsm;
    float* s_cxk = (float*)(dynsm + CXK_OFF);

    __shared__ float s_red[4][17];
    __shared__ float2 s_mid;

    // ---- per-CTA min/max over concat(xc, xt) ----
    float mn0 = 1e30f, mx0 = -1e30f, mn1 = 1e30f, mx1 = -1e30f;
    for (int idx = tid; idx < NC + NT; idx += NTHR) {
        const float2 p = (idx < NC)
            ? *(const float2*)(xc + (size_t)(b * NC + idx) * 2)
            : *(const float2*)(xt + (size_t)(b * NT + idx - NC) * 2);
        mn0 = fminf(mn0, p.x); mx0 = fmaxf(mx0, p.x);
        mn1 = fminf(mn1, p.y); mx1 = fmaxf(mx1, p.y);
    }
    for (int o = 16; o; o >>= 1) {
        mn0 = fminf(mn0, __shfl_xor_sync(~0u, mn0, o));
        mx0 = fmaxf(mx0, __shfl_xor_sync(~0u, mx0, o));
        mn1 = fminf(mn1, __shfl_xor_sync(~0u, mn1, o));
        mx1 = fmaxf(mx1, __shfl_xor_sync(~0u, mx1, o));
    }
    if (l == 0) { s_red[0][w] = mn0; s_red[1][w] = mx0; s_red[2][w] = mn1; s_red[3][w] = mx1; }
    __syncthreads();
    if (tid == 0) {
        float a = s_red[0][0], bb = s_red[1][0], c = s_red[2][0], d = s_red[3][0];
        #pragma unroll
        for (int k = 1; k < 17; k++) {
            a = fminf(a, s_red[0][k]); bb = fmaxf(bb, s_red[1][k]);
            c = fminf(c, s_red[2][k]); d = fmaxf(d, s_red[3][k]);
        }
        s_mid = make_float2(0.5f * (a + bb), 0.5f * (c + d));
    }
    const float k0 = soft_k(lsp[0]);
    const float k1 = soft_k(lsp[1]);
    __syncthreads();
    const float2 mid = s_mid;

    // ---- prologue: fill cxk and wyy tables for this CTA's K-half & j-tile ----
    const int c0 = ks * KS;
    for (int c = tid; c < KS; c += NTHR)
        s_cxk[c] = xc[(size_t)(b * NC + c0 + c) * 2] * k0;
    for (int idx = tid; idx < KS * JTW; idx += NTHR) {
        const int c = idx >> 4, jj = idx & 15;
        const int j = jt * JTW + jj;
        const float vy = xc[(size_t)(b * NC + c0 + c) * 2 + 1];
        const float2 yv = *(const float2*)(yc + (size_t)(b * NC + c0 + c) * 2);
        float wv = 0.0f;
        if (j <= 128) {
            const float d = (mid.y + (float)(j - HALF) * INV_PPU - vy) * k1;
            wv = ex2f(-(d * d));
        }
        float* dst = wyyf + c * 48 + jj;
        dst[0] = wv * yv.x; dst[16] = wv * yv.y; dst[32] = wv;
    }
    __syncthreads();

    if (w < 16) {
        // ---- main warps: i = ig*32 + lane (0..127), j-quad jg ----
        const int ig = w & 3, jg = w >> 2;
        const int i = ig * 32 + l;
        const float axk = (mid.x + (float)(i - HALF) * INV_PPU) * k0;
        const uint32_t wya = smb + (uint32_t)jg * 16;

        unsigned long long acc[6] = {0, 0, 0, 0, 0, 0};   // [ch 0..2][pair 0..1]
        #pragma unroll 4
        for (int c = 0; c < KS; c++) {
            const float cx = s_cxk[c];
            const float dx = axk - cx;
            const float wxv = ex2f(dx * -dx);
            unsigned long long wxp; PACK2(wxp, wxv);
            unsigned long long q0a, q0b, q1a, q1b, q2a, q2b;
            asm("ld.shared.v2.u64 {%0,%1}, [%2];" : "=l"(q0a), "=l"(q0b) : "r"(wya + c * 192));
            asm("ld.shared.v2.u64 {%0,%1}, [%2];" : "=l"(q1a), "=l"(q1b) : "r"(wya + c * 192 + 64));
            asm("ld.shared.v2.u64 {%0,%1}, [%2];" : "=l"(q2a), "=l"(q2b) : "r"(wya + c * 192 + 128));
            FMA2(acc[0], wxp, q0a); FMA2(acc[1], wxp, q0b);
            FMA2(acc[2], wxp, q1a); FMA2(acc[3], wxp, q1b);
            FMA2(acc[4], wxp, q2a); FMA2(acc[5], wxp, q2b);
        }

        // store 12 partial floats: [ks][b][i][jt*16+jg*4 .. +3][3ch] contiguous
        float* pp = g_part + (((size_t)(ks * M_B + b) * 129 + i) * 144
                              + (size_t)(jt * JTW + jg * 4)) * 3;
        union { unsigned long long u; float f[2]; } v;
        #pragma unroll
        for (int ch = 0; ch < 3; ch++) {
            #pragma unroll
            for (int p = 0; p < 2; p++) {
                v.u = acc[ch * 2 + p];
                pp[(2 * p) * 3 + ch]     = v.f[0];
                pp[(2 * p + 1) * 3 + ch] = v.f[1];
            }
        }
    } else if (l < 16) {
        // ---- edge warp: i = 128 row, 16 j's (one per lane) ----
        const float axe = (mid.x + (float)(128 - HALF) * INV_PPU) * k0;
        float e0 = 0.f, e1 = 0.f, e2 = 0.f;
        #pragma unroll 4
        for (int c = 0; c < KS; c++) {
            const float cx = s_cxk[c];
            const float dx = axe - cx;
            const float wxv = ex2f(dx * -dx);
            const float y0 = wyyf[c * 48 + l];
            const float y1 = wyyf[c * 48 + 16 + l];
            const float y2 = wyyf[c * 48 + 32 + l];
            e0 = fmaf(wxv, y0, e0);
            e1 = fmaf(wxv, y1, e1);
            e2 = fmaf(wxv, y2, e2);
        }
        float* pp = g_part + (((size_t)(ks * M_B + b) * 129 + 128) * 144
                              + (size_t)(jt * JTW + l)) * 3;
        pp[0] = e0; pp[1] = e1; pp[2] = e2;
    }

    // ---- x_grid from ks == 0 CTAs (bit-exact forms) ----
    if (ks == 0) {
        for (int idx = tid; idx < AX * JTW; idx += NTHR) {
            const int i = idx >> 4, jj = idx & 15;
            const int j = jt * JTW + jj;
            if (j < AX) {
                float2* xg = (float2*)out + (size_t)(b * NG) + (size_t)i * AX + j;
                *xg = make_float2(mid.x + (float)(i - HALF) * INV_PPU,
                                  mid.y + (float)(j - HALF) * INV_PPU);
            }
        }
    }
}

// ---------------- Combine kernel: z = p0 + p1, repack to output layout ----------------
__global__ void __launch_bounds__(256) combine_kernel(float* __restrict__ out) {
    const int PHALF = M_B * 129 * 144 * 3;
    for (int idx = blockIdx.x * 256 + threadIdx.x; idx < TOT_Z; idx += gridDim.x * 256) {
        const int b = idx / (NG * 3);
        int rem = idx - b * (NG * 3);
        const int i = rem / (AX * 3);
        rem -= i * (AX * 3);
        const int j = rem / 3;
        const int ch = rem - j * 3;
        const size_t src = (((size_t)b * 129 + i) * 144 + j) * 3 + ch;
        out[(size_t)X_TOTAL + idx] = g_part[src] + g_part[PHALF + src];
    }
}

extern "C" void kernel_launch(void* const* d_in, const int* in_sizes, int n_in,
                              void* d_out, int out_size) {
    const float* xc  = (const float*)d_in[0];
    const float* yc  = (const float*)d_in[1];
    const float* xt  = (const float*)d_in[2];
    const float* lsp = (const float*)d_in[3];
    float* out = (float*)d_out;

    cudaFuncSetAttribute(main_kernel, cudaFuncAttributeMaxDynamicSharedMemorySize, SMEM_M);
    main_kernel<<<dim3(2 * NJT, M_B), NTHR, SMEM_M>>>(xc, yc, xt, lsp, out);
    combine_kernel<<<390, 256>>>(out);
}

// round 10
// speedup vs baseline: 1.5702x; 1.0447x over previous
#include <cuda_runtime.h>
#include <math.h>
#include <stdint.h>

// Problem constants (fixed by the seeded reference):
//   m=8, nc=1024, nt=512, dim=2, PPU=64 -> grid 129x129 per batch.
#define M_B   8
#define NC    1024
#define NT    512
#define AX    129
#define NG    (AX * AX)            // 16641
#define HALF  64
#define INV_PPU (1.0f / 64.0f)
#define X_TOTAL (M_B * NG * 2)
#define TOT_Z (M_B * NG * 3)       // 399384
#define PHALF (M_B * NG * 3)       // floats per K-half partial

#define NTHR  544                  // 17 warps: 16 main (4 ig x 4 jg) + 1 edge
#define KS    512                  // contexts per K-half
#define JTW   16                   // j columns per CTA
#define NJT   9                    // 9 x 16 = 144 j-slots >= 129

// Dynamic smem: wyy [512 c][3 ch][16 j] floats (98304 B) then cxk [512] (2048 B)
#define WYY_BYTES (KS * 192)
#define CXK_OFF   WYY_BYTES
#define SMEM_M    (WYY_BYTES + KS * 4)   // 100352

// K-split partial scratch in FINAL z layout: [ks 2][b][i][j][ch]
__device__ __align__(16) float g_part[2 * PHALF];   // 3.2 MB

__device__ __forceinline__ float ex2f(float x) {
    float r; asm("ex2.approx.f32 %0, %1;" : "=f"(r) : "f"(x)); return r;
}
__device__ __forceinline__ float soft_k(float p) {
    // weight = 2^(-((d*k)^2)), k = sqrt(0.5*log2(e)) / (1e-5 + softplus(p))
    float ls = 1e-5f + log1pf(expf(p));
    return sqrtf(0.5f * 1.44269504088896341f) / ls;
}
__device__ __forceinline__ uint32_t sm32(const void* p) {
    uint32_t a;
    asm("{ .reg .u64 t; cvta.to.shared.u64 t, %1; cvt.u32.u64 %0, t; }" : "=r"(a) : "l"(p));
    return a;
}
#define FMA2(acc, a, b) \
    asm("fma.rn.f32x2 %0, %1, %2, %0;" : "+l"(acc) : "l"(a), "l"(b))
#define PACK2(d, w) \
    asm("mov.b64 %0, {%1, %1};" : "=l"(d) : "f"(w))

extern __shared__ char dynsm[];

// ---------------- Main kernel: fused setconv with K-split partials ----------------
__global__ void __launch_bounds__(NTHR, 1)
main_kernel(const float* __restrict__ xc, const float* __restrict__ yc,
            const float* __restrict__ xt, const float* __restrict__ lsp,
            float* __restrict__ out) {
    const int ks = blockIdx.x & 1;          // K half
    const int jt = blockIdx.x >> 1;         // 0..8
    const int b  = blockIdx.y;
    const int tid = threadIdx.x;
    const int w = tid >> 5, l = tid & 31;
    const uint32_t smb = sm32(dynsm);
    float* wyyf  = (float*)dynsm;
    float* s_cxk = (float*)(dynsm + CXK_OFF);

    __shared__ float s_red[4][17];
    __shared__ float2 s_mid;

    // ---- per-CTA min/max over concat(xc, xt) ----
    float mn0 = 1e30f, mx0 = -1e30f, mn1 = 1e30f, mx1 = -1e30f;
    for (int idx = tid; idx < NC + NT; idx += NTHR) {
        const float2 p = (idx < NC)
            ? *(const float2*)(xc + (size_t)(b * NC + idx) * 2)
            : *(const float2*)(xt + (size_t)(b * NT + idx - NC) * 2);
        mn0 = fminf(mn0, p.x); mx0 = fmaxf(mx0, p.x);
        mn1 = fminf(mn1, p.y); mx1 = fmaxf(mx1, p.y);
    }
    for (int o = 16; o; o >>= 1) {
        mn0 = fminf(mn0, __shfl_xor_sync(~0u, mn0, o));
        mx0 = fmaxf(mx0, __shfl_xor_sync(~0u, mx0, o));
        mn1 = fminf(mn1, __shfl_xor_sync(~0u, mn1, o));
        mx1 = fmaxf(mx1, __shfl_xor_sync(~0u, mx1, o));
    }
    if (l == 0) { s_red[0][w] = mn0; s_red[1][w] = mx0; s_red[2][w] = mn1; s_red[3][w] = mx1; }
    __syncthreads();
    if (tid == 0) {
        float a = s_red[0][0], bb = s_red[1][0], c = s_red[2][0], d = s_red[3][0];
        #pragma unroll
        for (int k = 1; k < 17; k++) {
            a = fminf(a, s_red[0][k]); bb = fmaxf(bb, s_red[1][k]);
            c = fminf(c, s_red[2][k]); d = fmaxf(d, s_red[3][k]);
        }
        s_mid = make_float2(0.5f * (a + bb), 0.5f * (c + d));
    }
    const float k0 = soft_k(lsp[0]);
    const float k1 = soft_k(lsp[1]);
    __syncthreads();
    const float2 mid = s_mid;

    // ---- prologue: fill cxk and wyy tables for this CTA's K-half & j-tile ----
    const int c0 = ks * KS;
    for (int c = tid; c < KS; c += NTHR)
        s_cxk[c] = xc[(size_t)(b * NC + c0 + c) * 2] * k0;
    for (int idx = tid; idx < KS * JTW; idx += NTHR) {
        const int c = idx >> 4, jj = idx & 15;
        const int j = jt * JTW + jj;
        const float vy = xc[(size_t)(b * NC + c0 + c) * 2 + 1];
        const float2 yv = *(const float2*)(yc + (size_t)(b * NC + c0 + c) * 2);
        float wv = 0.0f;
        if (j <= 128) {
            const float d = (mid.y + (float)(j - HALF) * INV_PPU - vy) * k1;
            wv = ex2f(-(d * d));
        }
        float* dst = wyyf + c * 48 + jj;
        dst[0] = wv * yv.x; dst[16] = wv * yv.y; dst[32] = wv;
    }
    __syncthreads();

    if (w < 16) {
        // ---- main warps: i = ig*32 + lane (0..127), j-quad jg ----
        const int ig = w & 3, jg = w >> 2;
        const int i = ig * 32 + l;
        const float axk = (mid.x + (float)(i - HALF) * INV_PPU) * k0;
        const uint32_t wya = smb + (uint32_t)jg * 16;

        unsigned long long acc[6] = {0, 0, 0, 0, 0, 0};   // [ch 0..2][pair 0..1]
        #pragma unroll 8
        for (int c4 = 0; c4 < KS / 4; c4++) {
            const float4 cx4 = *(const float4*)(s_cxk + c4 * 4);
            #pragma unroll
            for (int u = 0; u < 4; u++) {
                const int c = c4 * 4 + u;
                const float cx = (u == 0) ? cx4.x : (u == 1) ? cx4.y : (u == 2) ? cx4.z : cx4.w;
                const float dx = axk - cx;
                const float wxv = ex2f(dx * -dx);
                unsigned long long wxp; PACK2(wxp, wxv);
                unsigned long long q0a, q0b, q1a, q1b, q2a, q2b;
                asm("ld.shared.v2.u64 {%0,%1}, [%2];" : "=l"(q0a), "=l"(q0b) : "r"(wya + c * 192));
                asm("ld.shared.v2.u64 {%0,%1}, [%2];" : "=l"(q1a), "=l"(q1b) : "r"(wya + c * 192 + 64));
                asm("ld.shared.v2.u64 {%0,%1}, [%2];" : "=l"(q2a), "=l"(q2b) : "r"(wya + c * 192 + 128));
                FMA2(acc[0], wxp, q0a); FMA2(acc[1], wxp, q0b);
                FMA2(acc[2], wxp, q1a); FMA2(acc[3], wxp, q1b);
                FMA2(acc[4], wxp, q2a); FMA2(acc[5], wxp, q2b);
            }
        }

        // guarded stores, tight final-z layout
        const int j0 = jt * JTW + jg * 4;
        union { unsigned long long u; float f[2]; } v;
        #pragma unroll
        for (int jj = 0; jj < 4; jj++) {
            const int j = j0 + jj;
            if (j < AX) {
                float* pp = g_part + (size_t)ks * PHALF
                          + ((size_t)(b * NG) + (size_t)i * AX + j) * 3;
                #pragma unroll
                for (int ch = 0; ch < 3; ch++) {
                    v.u = acc[ch * 2 + (jj >> 1)];
                    pp[ch] = v.f[jj & 1];
                }
            }
        }
    } else if (l < 16) {
        // ---- edge warp: i = 128 row, 16 j's (one per lane) ----
        const int j = jt * JTW + l;
        const float axe = (mid.x + (float)(128 - HALF) * INV_PPU) * k0;
        float e0 = 0.f, e1 = 0.f, e2 = 0.f;
        #pragma unroll 4
        for (int c = 0; c < KS; c++) {
            const float cx = s_cxk[c];
            const float dx = axe - cx;
            const float wxv = ex2f(dx * -dx);
            const float y0 = wyyf[c * 48 + l];
            const float y1 = wyyf[c * 48 + 16 + l];
            const float y2 = wyyf[c * 48 + 32 + l];
            e0 = fmaf(wxv, y0, e0);
            e1 = fmaf(wxv, y1, e1);
            e2 = fmaf(wxv, y2, e2);
        }
        if (j < AX) {
            float* pp = g_part + (size_t)ks * PHALF
                      + ((size_t)(b * NG) + (size_t)128 * AX + j) * 3;
            pp[0] = e0; pp[1] = e1; pp[2] = e2;
        }
    }

    // ---- x_grid from ks == 0 CTAs (bit-exact forms) ----
    if (ks == 0) {
        for (int idx = tid; idx < AX * JTW; idx += NTHR) {
            const int i = idx >> 4, jj = idx & 15;
            const int j = jt * JTW + jj;
            if (j < AX) {
                float2* xg = (float2*)out + (size_t)(b * NG) + (size_t)i * AX + j;
                *xg = make_float2(mid.x + (float)(i - HALF) * INV_PPU,
                                  mid.y + (float)(j - HALF) * INV_PPU);
            }
        }
    }
}

// ---------------- Combine kernel: out_z = p0 + p1 (pure vector add) ----------------
__global__ void __launch_bounds__(256) combine_kernel(float* __restrict__ out) {
    const int idx = blockIdx.x * 256 + threadIdx.x;
    if (idx < TOT_Z / 4) {
        const float4 a = ((const float4*)g_part)[idx];
        const float4 c = ((const float4*)(g_part + PHALF))[idx];
        float4 r;
        r.x = a.x + c.x; r.y = a.y + c.y; r.z = a.z + c.z; r.w = a.w + c.w;
        ((float4*)(out + X_TOTAL))[idx] = r;
    }
}

extern "C" void kernel_launch(void* const* d_in, const int* in_sizes, int n_in,
                              void* d_out, int out_size) {
    const float* xc  = (const float*)d_in[0];
    const float* yc  = (const float*)d_in[1];
    const float* xt  = (const float*)d_in[2];
    const float* lsp = (const float*)d_in[3];
    float* out = (float*)d_out;

    cudaFuncSetAttribute(main_kernel, cudaFuncAttributeMaxDynamicSharedMemorySize, SMEM_M);
    main_kernel<<<dim3(2 * NJT, M_B), NTHR, SMEM_M>>>(xc, yc, xt, lsp, out);
    combine_kernel<<<(TOT_Z / 4 + 255) / 256, 256>>>(out);
}

// round 11
// speedup vs baseline: 1.6522x; 1.0522x over previous
#include <cuda_runtime.h>
#include <math.h>
#include <stdint.h>

// Problem constants (fixed by the seeded reference):
//   m=8, nc=1024, nt=512, dim=2, PPU=64 -> grid 129x129 per batch.
#define M_B   8
#define NC    1024
#define NT    512
#define AX    129
#define NG    (AX * AX)            // 16641
#define HALF  64
#define INV_PPU (1.0f / 64.0f)
#define X_TOTAL (M_B * NG * 2)
#define TOT_Z (M_B * NG * 3)       // 399384
#define PHALF TOT_Z                // floats per K-split partial

#define NSPL  4                    // K-splits
#define KS    256                  // contexts per split
#define NTHR  288                  // 9 warps: 8 main (4 ig x 2 jg) + 1 edge
#define JTW   16                   // j columns per CTA
#define NJT   9                    // 9 x 16 = 144 >= 129

// Dynamic smem: wyy [256 c][3 ch][16 j] floats (49152 B) then cxk [256]
#define WYY_BYTES (KS * 192)
#define CXK_OFF   WYY_BYTES
#define SMEM_M    (WYY_BYTES + KS * 4)   // 50176

// K-split partial scratch in final z layout: [ks 4][b][i][j][ch]
__device__ __align__(16) float g_part[NSPL * PHALF];   // 6.4 MB

__device__ __forceinline__ float ex2f(float x) {
    float r; asm("ex2.approx.f32 %0, %1;" : "=f"(r) : "f"(x)); return r;
}
__device__ __forceinline__ float soft_k(float p) {
    // weight = 2^(-((d*k)^2)), k = sqrt(0.5*log2(e)) / (1e-5 + softplus(p))
    float ls = 1e-5f + log1pf(expf(p));
    return sqrtf(0.5f * 1.44269504088896341f) / ls;
}
__device__ __forceinline__ uint32_t sm32(const void* p) {
    uint32_t a;
    asm("{ .reg .u64 t; cvta.to.shared.u64 t, %1; cvt.u32.u64 %0, t; }" : "=r"(a) : "l"(p));
    return a;
}
#define FMA2(acc, a, b) \
    asm("fma.rn.f32x2 %0, %1, %2, %0;" : "+l"(acc) : "l"(a), "l"(b))
#define PACK2(d, w) \
    asm("mov.b64 %0, {%1, %1};" : "=l"(d) : "f"(w))

extern __shared__ char dynsm[];

// ---------------- Main kernel: fused setconv with K-split partials ----------------
__global__ void __launch_bounds__(NTHR, 2)
main_kernel(const float* __restrict__ xc, const float* __restrict__ yc,
            const float* __restrict__ xt, const float* __restrict__ lsp,
            float* __restrict__ out) {
    const int ks = blockIdx.x & 3;          // K split
    const int jt = blockIdx.x >> 2;         // 0..8
    const int b  = blockIdx.y;
    const int tid = threadIdx.x;
    const int w = tid >> 5, l = tid & 31;
    const uint32_t smb = sm32(dynsm);
    float* wyyf  = (float*)dynsm;
    float* s_cxk = (float*)(dynsm + CXK_OFF);

    __shared__ float s_red[4][9];
    __shared__ float2 s_mid;

    // ---- per-CTA min/max over concat(xc, xt) ----
    float mn0 = 1e30f, mx0 = -1e30f, mn1 = 1e30f, mx1 = -1e30f;
    for (int idx = tid; idx < NC + NT; idx += NTHR) {
        const float2 p = (idx < NC)
            ? *(const float2*)(xc + (size_t)(b * NC + idx) * 2)
            : *(const float2*)(xt + (size_t)(b * NT + idx - NC) * 2);
        mn0 = fminf(mn0, p.x); mx0 = fmaxf(mx0, p.x);
        mn1 = fminf(mn1, p.y); mx1 = fmaxf(mx1, p.y);
    }
    for (int o = 16; o; o >>= 1) {
        mn0 = fminf(mn0, __shfl_xor_sync(~0u, mn0, o));
        mx0 = fmaxf(mx0, __shfl_xor_sync(~0u, mx0, o));
        mn1 = fminf(mn1, __shfl_xor_sync(~0u, mn1, o));
        mx1 = fmaxf(mx1, __shfl_xor_sync(~0u, mx1, o));
    }
    if (l == 0) { s_red[0][w] = mn0; s_red[1][w] = mx0; s_red[2][w] = mn1; s_red[3][w] = mx1; }
    __syncthreads();
    if (tid == 0) {
        float a = s_red[0][0], bb = s_red[1][0], c = s_red[2][0], d = s_red[3][0];
        #pragma unroll
        for (int k = 1; k < 9; k++) {
            a = fminf(a, s_red[0][k]); bb = fmaxf(bb, s_red[1][k]);
            c = fminf(c, s_red[2][k]); d = fmaxf(d, s_red[3][k]);
        }
        s_mid = make_float2(0.5f * (a + bb), 0.5f * (c + d));
    }
    const float k0 = soft_k(lsp[0]);
    const float k1 = soft_k(lsp[1]);
    __syncthreads();
    const float2 mid = s_mid;

    // ---- prologue: cxk + wyy tables (wyy pre-multiplied by ex2(-cx^2)) ----
    const int c0 = ks * KS;
    for (int c = tid; c < KS; c += NTHR)
        s_cxk[c] = xc[(size_t)(b * NC + c0 + c) * 2] * k0;
    for (int idx = tid; idx < KS * JTW; idx += NTHR) {
        const int c = idx >> 4, jj = idx & 15;
        const int j = jt * JTW + jj;
        const float2 vxy = *(const float2*)(xc + (size_t)(b * NC + c0 + c) * 2);
        const float2 yv  = *(const float2*)(yc + (size_t)(b * NC + c0 + c) * 2);
        const float cx = vxy.x * k0;
        const float fx = ex2f(-(cx * cx));
        float wv = 0.0f;
        if (j <= 128) {
            const float d = (mid.y + (float)(j - HALF) * INV_PPU - vxy.y) * k1;
            wv = ex2f(-(d * d));
        }
        wv *= fx;
        float* dst = wyyf + c * 48 + jj;
        dst[0] = wv * yv.x; dst[16] = wv * yv.y; dst[32] = wv;
    }
    __syncthreads();

    if (w < 8) {
        // ---- main warps: i = ig*32 + lane, 8 j's (jg) x 3 ch ----
        const int ig = w & 3, jg = w >> 2;
        const int i = ig * 32 + l;
        const float axk = (mid.x + (float)(i - HALF) * INV_PPU) * k0;
        const float a2 = axk + axk;
        const float ai = -(axk * axk);
        const uint32_t wya = smb + (uint32_t)jg * 32;

        unsigned long long acc[12];    // [ch 0..2][pair 0..3]
        #pragma unroll
        for (int q = 0; q < 12; q++) acc[q] = 0;

        #pragma unroll 4
        for (int c4 = 0; c4 < KS / 4; c4++) {
            const float4 cx4 = *(const float4*)(s_cxk + c4 * 4);
            const uint32_t wb = wya + (uint32_t)c4 * 768;
            #pragma unroll
            for (int u = 0; u < 4; u++) {
                const float cx = (u == 0) ? cx4.x : (u == 1) ? cx4.y : (u == 2) ? cx4.z : cx4.w;
                const float wxv = ex2f(fmaf(a2, cx, ai));
                unsigned long long wxp; PACK2(wxp, wxv);
                unsigned long long q0, q1, q2, q3, q4, q5, q6, q7, q8, q9, qa, qb;
                const uint32_t ub = wb + (uint32_t)u * 192;
                asm("ld.shared.v2.u64 {%0,%1}, [%2];"     : "=l"(q0), "=l"(q1) : "r"(ub));
                asm("ld.shared.v2.u64 {%0,%1}, [%2+16];"  : "=l"(q2), "=l"(q3) : "r"(ub));
                asm("ld.shared.v2.u64 {%0,%1}, [%2+64];"  : "=l"(q4), "=l"(q5) : "r"(ub));
                asm("ld.shared.v2.u64 {%0,%1}, [%2+80];"  : "=l"(q6), "=l"(q7) : "r"(ub));
                asm("ld.shared.v2.u64 {%0,%1}, [%2+128];" : "=l"(q8), "=l"(q9) : "r"(ub));
                asm("ld.shared.v2.u64 {%0,%1}, [%2+144];" : "=l"(qa), "=l"(qb) : "r"(ub));
                FMA2(acc[0], wxp, q0); FMA2(acc[1], wxp, q1);
                FMA2(acc[2], wxp, q2); FMA2(acc[3], wxp, q3);
                FMA2(acc[4], wxp, q4); FMA2(acc[5], wxp, q5);
                FMA2(acc[6], wxp, q6); FMA2(acc[7], wxp, q7);
                FMA2(acc[8], wxp, q8); FMA2(acc[9], wxp, q9);
                FMA2(acc[10], wxp, qa); FMA2(acc[11], wxp, qb);
            }
        }

        // guarded stores, final-z layout
        const int j0 = jt * JTW + jg * 8;
        union { unsigned long long u; float f[2]; } v;
        #pragma unroll
        for (int jj = 0; jj < 8; jj++) {
            const int j = j0 + jj;
            if (j < AX) {
                float* pp = g_part + (size_t)ks * PHALF
                          + ((size_t)(b * NG) + (size_t)i * AX + j) * 3;
                #pragma unroll
                for (int ch = 0; ch < 3; ch++) {
                    v.u = acc[ch * 4 + (jj >> 1)];
                    pp[ch] = v.f[jj & 1];
                }
            }
        }
    } else if (l < 16) {
        // ---- edge warp: i = 128 row, 16 j's (one per lane) ----
        const int j = jt * JTW + l;
        const float axe = (mid.x + (float)(128 - HALF) * INV_PPU) * k0;
        const float a2e = axe + axe;
        const float aie = -(axe * axe);
        float e0 = 0.f, e1 = 0.f, e2 = 0.f;
        #pragma unroll 4
        for (int c = 0; c < KS; c++) {
            const float cx = s_cxk[c];
            const float wxv = ex2f(fmaf(a2e, cx, aie));
            e0 = fmaf(wxv, wyyf[c * 48 + l],      e0);
            e1 = fmaf(wxv, wyyf[c * 48 + 16 + l], e1);
            e2 = fmaf(wxv, wyyf[c * 48 + 32 + l], e2);
        }
        if (j < AX) {
            float* pp = g_part + (size_t)ks * PHALF
                      + ((size_t)(b * NG) + (size_t)128 * AX + j) * 3;
            pp[0] = e0; pp[1] = e1; pp[2] = e2;
        }
    }

    // ---- x_grid from ks == 0 CTAs (bit-exact forms) ----
    if (ks == 0) {
        for (int idx = tid; idx < AX * JTW; idx += NTHR) {
            const int i = idx >> 4, jj = idx & 15;
            const int j = jt * JTW + jj;
            if (j < AX) {
                float2* xg = (float2*)out + (size_t)(b * NG) + (size_t)i * AX + j;
                *xg = make_float2(mid.x + (float)(i - HALF) * INV_PPU,
                                  mid.y + (float)(j - HALF) * INV_PPU);
            }
        }
    }
}

// ---------------- Combine kernel: out_z = p0+p1+p2+p3, MLP-8 ----------------
__global__ void __launch_bounds__(256) combine_kernel(float* __restrict__ out) {
    const int n4 = TOT_Z / 4;          // 99846
    const int half = n4 / 2;           // 49923
    const int t = blockIdx.x * 256 + threadIdx.x;
    if (t < half) {
        const float4* p0 = (const float4*)g_part;
        const float4* p1 = (const float4*)(g_part + PHALF);
        const float4* p2 = (const float4*)(g_part + 2 * (size_t)PHALF);
        const float4* p3 = (const float4*)(g_part + 3 * (size_t)PHALF);
        const int iA = t, iB = t + half;
        const float4 a0 = __ldg(p0 + iA), a1 = __ldg(p1 + iA);
        const float4 a2 = __ldg(p2 + iA), a3 = __ldg(p3 + iA);
        const float4 b0 = __ldg(p0 + iB), b1 = __ldg(p1 + iB);
        const float4 b2 = __ldg(p2 + iB), b3 = __ldg(p3 + iB);
        float4 ra, rb;
        ra.x = (a0.x + a1.x) + (a2.x + a3.x); ra.y = (a0.y + a1.y) + (a2.y + a3.y);
        ra.z = (a0.z + a1.z) + (a2.z + a3.z); ra.w = (a0.w + a1.w) + (a2.w + a3.w);
        rb.x = (b0.x + b1.x) + (b2.x + b3.x); rb.y = (b0.y + b1.y) + (b2.y + b3.y);
        rb.z = (b0.z + b1.z) + (b2.z + b3.z); rb.w = (b0.w + b1.w) + (b2.w + b3.w);
        ((float4*)(out + X_TOTAL))[iA] = ra;
        ((float4*)(out + X_TOTAL))[iB] = rb;
    }
}

extern "C" void kernel_launch(void* const* d_in, const int* in_sizes, int n_in,
                              void* d_out, int out_size) {
    const float* xc  = (const float*)d_in[0];
    const float* yc  = (const float*)d_in[1];
    const float* xt  = (const float*)d_in[2];
    const float* lsp = (const float*)d_in[3];
    float* out = (float*)d_out;

    cudaFuncSetAttribute(main_kernel, cudaFuncAttributeMaxDynamicSharedMemorySize, SMEM_M);
    main_kernel<<<dim3(NSPL * NJT, M_B), NTHR, SMEM_M>>>(xc, yc, xt, lsp, out);
    combine_kernel<<<(TOT_Z / 8 + 255) / 256, 256>>>(out);
}